// round 17
// baseline (speedup 1.0000x reference)
#include <cuda_runtime.h>
#include <cuda_fp16.h>
#include <cstdint>

#define IGNORE_INDEX (-100)
static constexpr int B_ = 4, S_ = 2048, D_ = 2048, V_ = 32000;
static constexpr int NROWS  = B_ * (S_ - 1);   // 8188
static constexpr int MPAD   = 8192;
static constexpr int MTILES = MPAD / 128;      // 64
static constexpr int NT     = 128;             // v-chunk width
static constexpr int VCHUNKS = V_ / NT;        // 250
static constexpr int VPAIRS  = VCHUNKS / 2;    // 125 (2 chunks per CTA)
static constexpr int KC     = 64;              // K per stage
static constexpr int KITERS = D_ / KC;         // 32
static constexpr int NCHUNK2 = 2 * KITERS;     // 64 chunks per CTA
static constexpr int A_ELEMS = 128 * KC;       // 8192
static constexpr int B_ELEMS = NT * KC;        // 8192
static constexpr int A_BYTES = A_ELEMS * 2;    // 16384
static constexpr int B_BYTES = B_ELEMS * 2;    // 16384
static constexpr int STAGE_BYTES = A_BYTES + B_BYTES;   // 32768
static constexpr int NSTAGE = 3;
// [0..48) mbarriers (3 full + 3 empty), [1024..2048) red-max, [2048..3072) red-sum
static constexpr int O_RED  = 1024;
static constexpr int O_STAGE = 3072;
static constexpr int SMEM_REQ = 1023 + O_STAGE + NSTAGE * STAGE_BYTES;  // 102399

// prep kernel grid sections (16 elems = two 16B stores per thread)
static constexpr int HQ_BLOCKS  = (MPAD * (D_ / 16)) / 256;  // 4096
static constexpr int WQ_BLOCKS  = (V_ * (D_ / 16)) / 256;    // 16000
static constexpr int LAB_BLOCKS = MPAD / 256;                // 32
static constexpr int PREP_BLOCKS = HQ_BLOCKS + WQ_BLOCKS + LAB_BLOCKS;

__device__ __align__(1024) __half g_h[(size_t)MPAD * D_];
__device__ __align__(1024) __half g_w[(size_t)V_ * D_];
__device__ int   g_lab[MPAD];
__device__ float g_plse[(size_t)VCHUNKS * MPAD];   // fused per-chunk partial lse
__device__ float g_gold[MPAD];
__device__ float g_bsum[32];
__device__ float g_bcnt[32];
__device__ int   g_done;

__device__ __forceinline__ uint32_t smem_u32(const void* p) {
    uint32_t a;
    asm("{ .reg .u64 t; cvta.to.shared.u64 t, %1; cvt.u32.u64 %0, t; }" : "=r"(a) : "l"(p));
    return a;
}
#define MBAR_INIT(a, c) \
    asm volatile("mbarrier.init.shared.b64 [%0], %1;" :: "r"(a), "r"(c) : "memory")
#define MBAR_EXPECT_TX(a, b) \
    asm volatile("mbarrier.arrive.expect_tx.shared.b64 _, [%0], %1;" :: "r"(a), "r"(b) : "memory")
#define MBAR_ARRIVE(a) \
    asm volatile("mbarrier.arrive.shared.b64 _, [%0];" :: "r"(a) : "memory")
#define MBAR_WAIT(mbar, ph) do {                                                        \
    uint32_t _m = (uint32_t)(mbar); uint32_t _p = (uint32_t)(ph); uint32_t _d;          \
    asm volatile("{\n\t.reg .pred p;\n\t"                                               \
        "mbarrier.try_wait.parity.acquire.cta.shared::cta.b64 p, [%1], %2;\n\t"         \
        "selp.b32 %0, 1, 0, p;\n\t}" : "=r"(_d) : "r"(_m), "r"(_p) : "memory");         \
    if (!_d) {                                                                          \
        asm volatile("{\n\t.reg .pred P1;\n"                                            \
            "WAIT_LOOP_%=:\n\t"                                                         \
            "mbarrier.try_wait.parity.acquire.cta.shared::cta.b64 P1, [%0], %1, 0x989680;\n\t" \
            "@P1 bra.uni WAIT_DONE_%=;\n\t"                                             \
            "bra.uni WAIT_LOOP_%=;\n"                                                   \
            "WAIT_DONE_%=:\n\t}" :: "r"(_m), "r"(_p) : "memory");                       \
    }                                                                                   \
} while (0)
#define BULK_G2S(dst, src, bytes, mbar)                                                 \
    asm volatile("cp.async.bulk.shared::cluster.global.mbarrier::complete_tx::bytes "   \
                 "[%0], [%1], %2, [%3];"                                                \
                 :: "r"(dst), "l"(src), "r"(bytes), "r"(mbar) : "memory")
#define FENCE_PROXY() asm volatile("fence.proxy.async.shared::cta;" ::: "memory")

#define LDSM_X4(r0, r1, r2, r3, addr) \
    asm volatile("ldmatrix.sync.aligned.m8n8.x4.shared.b16 {%0,%1,%2,%3}, [%4];" \
        : "=r"(r0), "=r"(r1), "=r"(r2), "=r"(r3) : "r"(addr))

#define MMA16816(d, a0, a1, a2, a3, b0, b1) \
    asm volatile("mma.sync.aligned.m16n8k16.row.col.f32.f16.f16.f32 " \
        "{%0,%1,%2,%3}, {%4,%5,%6,%7}, {%8,%9}, {%0,%1,%2,%3};" \
        : "+f"((d)[0]), "+f"((d)[1]), "+f"((d)[2]), "+f"((d)[3]) \
        : "r"(a0), "r"(a1), "r"(a2), "r"(a3), "r"(b0), "r"(b1))

__device__ __forceinline__ uint32_t swz128(uint32_t b) { return b ^ ((b >> 3) & 0x70); }

// pack 8 floats -> 8 fp16 in one uint4
__device__ __forceinline__ uint4 pack8(const float4& a, const float4& b) {
    uint4 r;
    __half2 h0 = __floats2half2_rn(a.x, a.y), h1 = __floats2half2_rn(a.z, a.w);
    __half2 h2 = __floats2half2_rn(b.x, b.y), h3 = __floats2half2_rn(b.z, b.w);
    r.x = *reinterpret_cast<uint32_t*>(&h0);
    r.y = *reinterpret_cast<uint32_t*>(&h1);
    r.z = *reinterpret_cast<uint32_t*>(&h2);
    r.w = *reinterpret_cast<uint32_t*>(&h3);
    return r;
}

// ---- fused prep: pack h (shifted) + pack W into tiled+swizzled fp16, and
//      build shifted labels + reset the reduce ticket. One launch. ----
__global__ void k_prep(const float* __restrict__ hs, const float* __restrict__ w,
                       const long long* __restrict__ labels) {
    int bx = blockIdx.x;
    if (bx < HQ_BLOCKS) {
        size_t idx = (size_t)bx * 256 + threadIdx.x;   // h 16-elem index
        int n = (int)(idx >> 7);                       // 128 per row
        int d = (int)(idx & 127) * 16;
        float4 v0 = make_float4(0.f, 0.f, 0.f, 0.f), v1 = v0, v2 = v0, v3 = v0;
        if (n < NROWS) {
            int b = n / (S_ - 1), s = n % (S_ - 1);
            const float* p = hs + ((size_t)(b * S_ + s) * D_ + d);
            v0 = *reinterpret_cast<const float4*>(p);
            v1 = *reinterpret_cast<const float4*>(p + 4);
            v2 = *reinterpret_cast<const float4*>(p + 8);
            v3 = *reinterpret_cast<const float4*>(p + 12);
        }
        int kit = d >> 6, c = d & 63;
        size_t tile = ((size_t)((n >> 7) * KITERS + kit)) << 13;
        char* tb = reinterpret_cast<char*>(g_h + tile);
        uint32_t byte = (uint32_t)(n & 127) * 128u + (uint32_t)c * 2u;   // 16B-aligned
        *reinterpret_cast<uint4*>(tb + swz128(byte))      = pack8(v0, v1);
        *reinterpret_cast<uint4*>(tb + swz128(byte + 16)) = pack8(v2, v3);
    } else if (bx < HQ_BLOCKS + WQ_BLOCKS) {
        size_t idx = (size_t)(bx - HQ_BLOCKS) * 256 + threadIdx.x;   // w 16-elem index
        int v = (int)(idx >> 7);
        int d = (int)(idx & 127) * 16;
        const float* p = w + (size_t)v * D_ + d;
        float4 v0 = *reinterpret_cast<const float4*>(p);
        float4 v1 = *reinterpret_cast<const float4*>(p + 4);
        float4 v2 = *reinterpret_cast<const float4*>(p + 8);
        float4 v3 = *reinterpret_cast<const float4*>(p + 12);
        int kit = d >> 6, c = d & 63;
        size_t tile = ((size_t)((v >> 7) * KITERS + kit)) << 13;
        char* tb = reinterpret_cast<char*>(g_w + tile);
        uint32_t byte = (uint32_t)(v & 127) * 128u + (uint32_t)c * 2u;
        *reinterpret_cast<uint4*>(tb + swz128(byte))      = pack8(v0, v1);
        *reinterpret_cast<uint4*>(tb + swz128(byte + 16)) = pack8(v2, v3);
    } else {
        int n = (bx - HQ_BLOCKS - WQ_BLOCKS) * 256 + threadIdx.x;
        if (n < MPAD) {
            int v = -1;
            if (n < NROWS) {
                int b = n / (S_ - 1), s = n % (S_ - 1);
                long long t = labels[b * S_ + s + 1];
                v = (t != IGNORE_INDEX && t >= 0 && t < V_) ? (int)t : -1;
            }
            g_lab[n] = v;
        }
        if (n == 0) g_done = 0;   // reset reduce finalize ticket every call
    }
}

// ---- fused GEMM (mma.sync fp16) + partial logsumexp + gold extraction ----
// 256 threads, 2 CTAs/SM. Each CTA processes TWO adjacent v-chunks
// (2*by, 2*by+1) over the same A tile as a single 64-chunk pipeline stream
// (their W tiles are contiguous in g_w). The vc0 epilogue runs with the
// pipeline warm — chunks 32,33 prefetched at g=30,31. Halves CTA launches
// and pipeline fills; HW still load-balances 8000 CTAs.
__global__ void __launch_bounds__(256, 2) k_gemm_lse() {
    extern __shared__ char smem_raw[];
    const uint32_t raw = smem_u32(smem_raw);
    const uint32_t sb = (raw + 1023u) & ~1023u;
    const uint32_t pad = sb - raw;
    float* s_redm = reinterpret_cast<float*>(smem_raw + pad + O_RED);         // [128][2]
    float* s_reds = reinterpret_cast<float*>(smem_raw + pad + O_RED + 1024);  // [128][2]
    const uint32_t o_full  = sb;        // 3 mbarriers (tx-based fills)
    const uint32_t o_empty = sb + 24;   // 3 mbarriers (count=256 consumer arrivals)
    const uint32_t o_stage = sb + O_STAGE;

    const int tid = threadIdx.x;
    const int wid = tid >> 5, l = tid & 31;
    const int mw = wid & 3, nw = wid >> 2;          // 4 M-warps x 2 N-warps
    const int wm = mw * 32, wn = nw * 64;

    if (tid == 0) {
        MBAR_INIT(o_full + 0, 1);   MBAR_INIT(o_full + 8, 1);   MBAR_INIT(o_full + 16, 1);
        MBAR_INIT(o_empty + 0, 256); MBAR_INIT(o_empty + 8, 256); MBAR_INIT(o_empty + 16, 256);
        FENCE_PROXY();
    }
    __syncthreads();

    const int mt = blockIdx.x, vc0 = blockIdx.y * 2;
    const __half* ha = g_h + (size_t)mt * ((size_t)KITERS * A_ELEMS);
    const __half* wb = g_w + (size_t)vc0 * ((size_t)KITERS * B_ELEMS);  // 64 tiles contiguous

    if (tid == 0) {
        #pragma unroll
        for (int p = 0; p < NSTAGE; ++p) {
            MBAR_EXPECT_TX(o_full + 8 * p, STAGE_BYTES);
            BULK_G2S(o_stage + p * STAGE_BYTES,           ha + (size_t)p * A_ELEMS, A_BYTES, o_full + 8 * p);
            BULK_G2S(o_stage + p * STAGE_BYTES + A_BYTES, wb + (size_t)p * B_ELEMS, B_BYTES, o_full + 8 * p);
        }
    }

    // per-lane ldmatrix address components (swizzle mask depends only on row%8)
    const uint32_t a_row = (uint32_t)(wm + (l & 15));
    const uint32_t a_base = a_row * 128u;
    const uint32_t a_mask = (a_row & 7u) << 4;
    const uint32_t a_cb = (uint32_t)((l >> 4) * 16);
    const uint32_t b_row = (uint32_t)(wn + (l & 7) + ((l >> 4) << 3));
    const uint32_t b_base = b_row * 128u;
    const uint32_t b_mask = (b_row & 7u) << 4;
    const uint32_t b_cb = (uint32_t)(((l >> 3) & 1) * 16);

    float acc[2][8][4];
    #pragma unroll
    for (int i = 0; i < 2; ++i)
        #pragma unroll
        for (int j = 0; j < 8; ++j)
            #pragma unroll
            for (int q = 0; q < 4; ++q) acc[i][j][q] = 0.f;

    int s = 0, ph = 0;
    for (int half = 0; half < 2; ++half) {
        const int vc = vc0 + half;
        for (int it = 0; it < KITERS; ++it) {
            const int g = half * KITERS + it;       // global chunk counter 0..63
            // Deferred refill: service the stage freed at chunk g-1 with
            // chunk g+2. Producer rotates: lane 0 of warp (g & 7).
            if (g >= 1 && g + 2 < NCHUNK2 && tid == ((g & 7) << 5)) {
                const int sp = (g - 1) % NSTAGE;
                const int c = g + 2;
                const uint32_t pA = o_stage + sp * STAGE_BYTES;
                MBAR_WAIT(o_empty + 8 * sp, ((g - 1) / NSTAGE) & 1);
                MBAR_EXPECT_TX(o_full + 8 * sp, STAGE_BYTES);
                BULK_G2S(pA,           ha + (size_t)(c & 31) * A_ELEMS, A_BYTES, o_full + 8 * sp);
                BULK_G2S(pA + A_BYTES, wb + (size_t)c * B_ELEMS,       B_BYTES, o_full + 8 * sp);
            }
            MBAR_WAIT(o_full + 8 * s, ph);
            const uint32_t stA = o_stage + s * STAGE_BYTES;
            const uint32_t stB = stA + A_BYTES;
            #pragma unroll
            for (int kk = 0; kk < 4; ++kk) {
                uint32_t a0[4], a1[4], b[4][4];
                const uint32_t aAdr = stA + a_base + ((a_cb + kk * 32u) ^ a_mask);
                LDSM_X4(a0[0], a0[1], a0[2], a0[3], aAdr);
                LDSM_X4(a1[0], a1[1], a1[2], a1[3], aAdr + 2048u);
                const uint32_t bAdr = stB + b_base + ((b_cb + kk * 32u) ^ b_mask);
                #pragma unroll
                for (int j = 0; j < 4; ++j)
                    LDSM_X4(b[j][0], b[j][1], b[j][2], b[j][3], bAdr + (uint32_t)j * 2048u);
                #pragma unroll
                for (int j = 0; j < 4; ++j) {
                    MMA16816(acc[0][2 * j],     a0[0], a0[1], a0[2], a0[3], b[j][0], b[j][1]);
                    MMA16816(acc[1][2 * j],     a1[0], a1[1], a1[2], a1[3], b[j][0], b[j][1]);
                    MMA16816(acc[0][2 * j + 1], a0[0], a0[1], a0[2], a0[3], b[j][2], b[j][3]);
                    MMA16816(acc[1][2 * j + 1], a1[0], a1[1], a1[2], a1[3], b[j][2], b[j][3]);
                }
            }
            MBAR_ARRIVE(o_empty + 8 * s);   // release: my reads of stage s done
            if (++s == NSTAGE) { s = 0; ph ^= 1; }
        }

        // ---- gold extraction for this chunk's columns ----
        #pragma unroll
        for (int sl = 0; sl < 4; ++sl) {
            int row = wm + (sl >> 1) * 16 + (sl & 1) * 8 + (l >> 2);
            int t = g_lab[mt * 128 + row];
            int local = t - vc * NT - wn;
            if (local >= 0 && local < 64) {
                int mti = sl >> 1, h = sl & 1;
                #pragma unroll
                for (int j = 0; j < 8; ++j)
                    #pragma unroll
                    for (int c = 0; c < 2; ++c) {
                        int coln = (j >> 1) * 16 + (j & 1) * 8 + (l & 3) * 2 + c;
                        if (coln == local)
                            g_gold[mt * 128 + row] = acc[mti][j][2 * h + c];
                    }
            }
        }

        // ---- epilogue: per-row max & sum(exp) over this chunk's 128 cols ----
        // (pipeline keeps streaming: chunks g+2 were prefetched at g=30,31)
        float mx[4];
        #pragma unroll
        for (int mti = 0; mti < 2; ++mti)
            #pragma unroll
            for (int h = 0; h < 2; ++h) {
                float m = -1e30f;
                #pragma unroll
                for (int j = 0; j < 8; ++j)
                    m = fmaxf(m, fmaxf(acc[mti][j][2 * h], acc[mti][j][2 * h + 1]));
                m = fmaxf(m, __shfl_xor_sync(0xffffffffu, m, 1));
                m = fmaxf(m, __shfl_xor_sync(0xffffffffu, m, 2));
                mx[mti * 2 + h] = m;
            }
        if ((l & 3) == 0) {
            #pragma unroll
            for (int sl = 0; sl < 4; ++sl) {
                int row = wm + (sl >> 1) * 16 + (sl & 1) * 8 + (l >> 2);
                s_redm[row * 2 + nw] = mx[sl];
            }
        }
        __syncthreads();
        float fm[4], sm[4];
        #pragma unroll
        for (int sl = 0; sl < 4; ++sl) {
            int row = wm + (sl >> 1) * 16 + (sl & 1) * 8 + (l >> 2);
            float m = fmaxf(s_redm[row * 2 + 0], s_redm[row * 2 + 1]);
            fm[sl] = m;
            int mti = sl >> 1, h = sl & 1;
            float ss = 0.f;
            #pragma unroll
            for (int j = 0; j < 8; ++j)
                ss += __expf(acc[mti][j][2 * h] - m) + __expf(acc[mti][j][2 * h + 1] - m);
            ss += __shfl_xor_sync(0xffffffffu, ss, 1);
            ss += __shfl_xor_sync(0xffffffffu, ss, 2);
            sm[sl] = ss;
        }
        if ((l & 3) == 0) {
            #pragma unroll
            for (int sl = 0; sl < 4; ++sl) {
                int row = wm + (sl >> 1) * 16 + (sl & 1) * 8 + (l >> 2);
                s_reds[row * 2 + nw] = sm[sl];
            }
        }
        __syncthreads();
        if (nw == 0 && (l & 3) == 0) {
            #pragma unroll
            for (int sl = 0; sl < 4; ++sl) {
                int row = wm + (sl >> 1) * 16 + (sl & 1) * 8 + (l >> 2);
                float tot = s_reds[row * 2 + 0] + s_reds[row * 2 + 1];
                size_t g = (size_t)vc * MPAD + (size_t)mt * 128 + row;
                g_plse[g] = fm[sl] + __logf(tot);   // fused partial lse
            }
        }
        // reset accumulators for second chunk
        if (half == 0) {
            #pragma unroll
            for (int i = 0; i < 2; ++i)
                #pragma unroll
                for (int j = 0; j < 8; ++j)
                    #pragma unroll
                    for (int q = 0; q < 4; ++q) acc[i][j][q] = 0.f;
        }
    }
}

// ---- combine fused partials; block sums + last-block finalize ----
__global__ void k_reduce(float* __restrict__ out) {
    __shared__ float s_nll[256], s_cnt[256];
    int row = blockIdx.x * 256 + threadIdx.x;
    float nll = 0.f, cnt = 0.f;
    if (row < NROWS) {
        int t = g_lab[row];
        if (t >= 0) {
            float m = -1e30f;
            for (int c = 0; c < VCHUNKS; ++c)
                m = fmaxf(m, g_plse[(size_t)c * MPAD + row]);
            float ss = 0.f;
            for (int c = 0; c < VCHUNKS; ++c)
                ss += __expf(g_plse[(size_t)c * MPAD + row] - m);
            nll = m + __logf(ss) - g_gold[row];
            cnt = 1.f;
        }
    }
    s_nll[threadIdx.x] = nll; s_cnt[threadIdx.x] = cnt;
    __syncthreads();
    for (int o = 128; o; o >>= 1) {
        if (threadIdx.x < o) {
            s_nll[threadIdx.x] += s_nll[threadIdx.x + o];
            s_cnt[threadIdx.x] += s_cnt[threadIdx.x + o];
        }
        __syncthreads();
    }
    if (threadIdx.x == 0) {
        g_bsum[blockIdx.x] = s_nll[0];
        g_bcnt[blockIdx.x] = s_cnt[0];
        __threadfence();
        int t = atomicAdd(&g_done, 1);
        if (t == 31) {   // last block: deterministic fixed-order final sum
            float s = 0.f, c = 0.f;
            for (int i = 0; i < 32; ++i) { s += g_bsum[i]; c += g_bcnt[i]; }
            out[0] = s / fmaxf(c, 1.f);
        }
    }
}

extern "C" void kernel_launch(void* const* d_in, const int* in_sizes, int n_in,
                              void* d_out, int out_size) {
    const float* hs = (const float*)d_in[0];
    const float* w  = (const float*)d_in[1];
    const long long* labels = (const long long*)d_in[2];
    float* out = (float*)d_out;
    cudaFuncSetAttribute(k_gemm_lse, cudaFuncAttributeMaxDynamicSharedMemorySize, SMEM_REQ);
    k_prep<<<PREP_BLOCKS, 256>>>(hs, w, labels);
    dim3 grid(MTILES, VPAIRS);
    k_gemm_lse<<<grid, 256, SMEM_REQ>>>();
    k_reduce<<<32, 256>>>(out);
}